// round 8
// baseline (speedup 1.0000x reference)
#include <cuda_runtime.h>
#include <cuda_bf16.h>

// Problem constants
#define L 3
#define B 2
#define C 2048
#define HW 3600          // 60*60
#define CH 256
#define KD (L*C)         // 6144, fused K dimension
#define TEMP 20.0f
#define ATT_WT 0.3f

// ---------------- scratch (static __device__ — no allocations) ----------------
__device__ float g_Aq[(size_t)B * KD * HW];   // [b][k][q]  w_l * normalized fq (fp32)
__device__ float g_As[(size_t)B * KD * HW];   // [b][k][s]  normalized fs (fp32)
__device__ float g_red[(size_t)B * HW * HW];  // [b][q][s]  logits -> attn
__device__ float g_invq[L * B * HW];
__device__ float g_invs[L * B * HW];

// ---------------- 1) inverse norms over C (coalesced over spatial) ------------
__global__ void norm_kernel(const float* __restrict__ x, int which) {
    float* inv = which ? g_invs : g_invq;
    int p = blockIdx.x * blockDim.x + threadIdx.x;
    int lb = blockIdx.y;                    // l*B + b
    if (p >= HW) return;
    const float* base = x + (size_t)lb * C * HW + p;
    float s = 0.f;
    #pragma unroll 8
    for (int c = 0; c < C; c++) {
        float v = base[(size_t)c * HW];
        s += v * v;
    }
    float n = sqrtf(s);
    inv[lb * HW + p] = 1.0f / fmaxf(n, 1e-12f);
}

// ---------------- 2) scale + pack (fp32) in [b][k][p] layout ------------------
__global__ void pack_kernel(const float* __restrict__ x, const float* __restrict__ wts,
                            int which) {
    const float* inv = which ? g_invs : g_invq;
    float* out = which ? g_As : g_Aq;
    size_t idx = (size_t)blockIdx.x * blockDim.x + threadIdx.x;
    const size_t total = (size_t)L * B * C * HW;
    if (idx >= total) return;
    int l = (int)(idx / ((size_t)B * C * HW));
    size_t r = idx % ((size_t)B * C * HW);
    int b = (int)(r / ((size_t)C * HW));
    size_t r2 = r % ((size_t)C * HW);
    int c = (int)(r2 / HW);
    int p = (int)(r2 % HW);
    float w = which ? 1.0f : wts[l];
    float v = x[idx] * inv[(l * B + b) * HW + p] * w;
    out[((size_t)b * KD + (size_t)(l * C + c)) * HW + p] = v;
}

// ---------------- 3) big GEMM: red[b][q][s] = sum_k Aq[b][k][q]*As[b][k][s] ---
#define BM 128
#define BN 128
#define BK 16

__global__ __launch_bounds__(256) void gemm1_kernel() {
    int b = blockIdx.z;
    const float* A  = g_Aq + (size_t)b * KD * HW;
    const float* Bm = g_As + (size_t)b * KD * HW;
    float* Cc = g_red + (size_t)b * HW * HW;

    __shared__ float As[BK][BM];
    __shared__ float Bs[BK][BN];

    int m0 = blockIdx.x * BM;
    int n0 = blockIdx.y * BN;
    int tid = threadIdx.x;
    int tx = tid & 15;      // n direction
    int ty = tid >> 4;      // m direction

    float acc[8][8];
    #pragma unroll
    for (int i = 0; i < 8; i++)
        #pragma unroll
        for (int j = 0; j < 8; j++) acc[i][j] = 0.f;

    for (int k0 = 0; k0 < KD; k0 += BK) {
        #pragma unroll
        for (int jj = 0; jj < 8; jj++) {
            int i = tid + jj * 256;
            int kk = i >> 7;
            int mm = i & 127;
            int m = m0 + mm;
            int n = n0 + mm;
            As[kk][mm] = (m < HW) ? A[(size_t)(k0 + kk) * HW + m] : 0.f;
            Bs[kk][mm] = (n < HW) ? Bm[(size_t)(k0 + kk) * HW + n] : 0.f;
        }
        __syncthreads();
        #pragma unroll
        for (int kk = 0; kk < BK; kk++) {
            float a[8], bb[8];
            #pragma unroll
            for (int i = 0; i < 8; i++) a[i] = As[kk][ty * 8 + i];
            #pragma unroll
            for (int j = 0; j < 8; j++) bb[j] = Bs[kk][tx * 8 + j];
            #pragma unroll
            for (int i = 0; i < 8; i++)
                #pragma unroll
                for (int j = 0; j < 8; j++)
                    acc[i][j] += a[i] * bb[j];
        }
        __syncthreads();
    }

    #pragma unroll
    for (int i = 0; i < 8; i++) {
        int m = m0 + ty * 8 + i;
        if (m >= HW) continue;
        #pragma unroll
        for (int j = 0; j < 8; j++) {
            int n = n0 + tx * 8 + j;
            if (n < HW) Cc[(size_t)m * HW + n] = acc[i][j];
        }
    }
}

// ---------------- 4) row softmax over s (in-place, temp applied) --------------
__global__ __launch_bounds__(256) void softmax_kernel() {
    __shared__ float row[HW];
    __shared__ float sred[256];
    size_t base = (size_t)blockIdx.x * HW;   // blockIdx.x = b*HW + q
    int tid = threadIdx.x;

    float mx = -1e30f;
    for (int s = tid; s < HW; s += 256) {
        float v = g_red[base + s] * TEMP;
        row[s] = v;
        mx = fmaxf(mx, v);
    }
    sred[tid] = mx;
    __syncthreads();
    for (int st = 128; st > 0; st >>= 1) {
        if (tid < st) sred[tid] = fmaxf(sred[tid], sred[tid + st]);
        __syncthreads();
    }
    mx = sred[0];
    __syncthreads();

    float sm = 0.f;
    for (int s = tid; s < HW; s += 256) {
        float e = __expf(row[s] - mx);
        row[s] = e;
        sm += e;
    }
    sred[tid] = sm;
    __syncthreads();
    for (int st = 128; st > 0; st >>= 1) {
        if (tid < st) sred[tid] += sred[tid + st];
        __syncthreads();
    }
    float invs = 1.0f / sred[0];
    for (int s = tid; s < HW; s += 256)
        g_red[base + s] = row[s] * invs;
}

// ---------------- 5) attn GEMM + fused epilogue -------------------------------
// att_fq[b][c][q] = sum_s attn[b][q][s] * f_s[b][c][s]
#define BM2 64
#define BN2 64
#define BK2 32

__global__ __launch_bounds__(256) void gemm2_kernel(const float* __restrict__ v,
                                                    const float* __restrict__ fqin,
                                                    float* __restrict__ outfq,
                                                    float* __restrict__ outatt) {
    int b = blockIdx.z;
    const float* A  = g_red + (size_t)b * HW * HW;   // [q][s]
    const float* Bv = v + (size_t)b * CH * HW;       // [c][s]

    int m0 = blockIdx.x * BM2;   // q
    int n0 = blockIdx.y * BN2;   // c

    __shared__ float As[BM2][BK2 + 1];
    __shared__ float Bs[BN2][BK2 + 1];

    int tid = threadIdx.x;
    int tx = tid & 15;      // m (q) direction -> coalesced output
    int ty = tid >> 4;      // n (c) direction

    float acc[4][4];   // acc[j (n)][i (m)]
    #pragma unroll
    for (int j = 0; j < 4; j++)
        #pragma unroll
        for (int i = 0; i < 4; i++) acc[j][i] = 0.f;

    for (int k0 = 0; k0 < HW; k0 += BK2) {
        #pragma unroll
        for (int jj = 0; jj < 8; jj++) {
            int i = tid + jj * 256;
            int mm = i >> 5;
            int kk = i & 31;
            int m = m0 + mm;
            int k = k0 + kk;
            As[mm][kk] = (m < HW && k < HW) ? A[(size_t)m * HW + k] : 0.f;
            int n = n0 + mm;
            Bs[mm][kk] = (k < HW) ? Bv[(size_t)n * HW + k] : 0.f;
        }
        __syncthreads();
        #pragma unroll
        for (int kk = 0; kk < BK2; kk++) {
            float a[4], bb[4];
            #pragma unroll
            for (int i = 0; i < 4; i++) a[i] = As[tx * 4 + i][kk];
            #pragma unroll
            for (int j = 0; j < 4; j++) bb[j] = Bs[ty * 4 + j][kk];
            #pragma unroll
            for (int j = 0; j < 4; j++)
                #pragma unroll
                for (int i = 0; i < 4; i++)
                    acc[j][i] += a[i] * bb[j];
        }
        __syncthreads();
    }

    const float inv13 = 1.0f / (1.0f + ATT_WT);
    #pragma unroll
    for (int j = 0; j < 4; j++) {
        int n = n0 + ty * 4 + j;     // c (always < CH)
        #pragma unroll
        for (int i = 0; i < 4; i++) {
            int m = m0 + tx * 4 + i; // q
            if (m < HW) {
                size_t o = ((size_t)b * CH + n) * HW + m;
                float av = acc[j][i];
                outatt[o] = av;
                outfq[o] = (fqin[o] + av * ATT_WT) * inv13;
            }
        }
    }
}

// ---------------- launch ------------------------------------------------------
extern "C" void kernel_launch(void* const* d_in, const int* in_sizes, int n_in,
                              void* d_out, int out_size) {
    const float* fq_feats = (const float*)d_in[0];
    const float* fs_feats = (const float*)d_in[1];
    const float* f_q      = (const float*)d_in[2];
    const float* f_s      = (const float*)d_in[3];
    const float* w        = (const float*)d_in[4];

    float* outfq  = (float*)d_out;
    float* outatt = outfq + (size_t)B * CH * HW;

    // 1) inverse norms
    dim3 gN((HW + 255) / 256, L * B);
    norm_kernel<<<gN, 256>>>(fq_feats, 0);
    norm_kernel<<<gN, 256>>>(fs_feats, 1);

    // 2) pack (fp32) to [b][k][p]
    size_t total = (size_t)L * B * C * HW;
    int pb = (int)((total + 255) / 256);
    pack_kernel<<<pb, 256>>>(fq_feats, w, 0);
    pack_kernel<<<pb, 256>>>(fs_feats, w, 1);

    // 3) red = (w-scaled fq_n)^T @ fs_n   (M=N=3600, K=6144, per batch)
    dim3 g1((HW + BM - 1) / BM, (HW + BN - 1) / BN, B);
    gemm1_kernel<<<g1, 256>>>();

    // 4) softmax over support positions
    softmax_kernel<<<B * HW, 256>>>();

    // 5) attn @ v + epilogue
    dim3 g2((HW + BM2 - 1) / BM2, CH / BN2, B);
    gemm2_kernel<<<g2, 256>>>(f_s, f_q, outfq, outatt);
}

// round 9
// speedup vs baseline: 1.0023x; 1.0023x over previous
#include <cuda_runtime.h>
#include <cuda_bf16.h>

// Problem constants
#define L 3
#define B 2
#define C 2048
#define HW 3600          // 60*60
#define CH 256
#define KD (L*C)         // 6144, fused K dimension
#define TEMP 20.0f
#define ATT_WT 0.3f

// ---------------- scratch (static __device__ — no allocations) ----------------
__device__ float g_Aq[(size_t)B * KD * HW];   // [b][k][q]  w_l * normalized fq (fp32)
__device__ float g_As[(size_t)B * KD * HW];   // [b][k][s]  normalized fs (fp32)
__device__ float g_red[(size_t)B * HW * HW];  // [b][q][s]  logits -> attn
__device__ float g_invq[L * B * HW];
__device__ float g_invs[L * B * HW];

// ---------------- 1) inverse norms over C (coalesced over spatial) ------------
__global__ void norm_kernel(const float* __restrict__ x, int which) {
    float* inv = which ? g_invs : g_invq;
    int p = blockIdx.x * blockDim.x + threadIdx.x;
    int lb = blockIdx.y;                    // l*B + b
    if (p >= HW) return;
    const float* base = x + (size_t)lb * C * HW + p;
    float s = 0.f;
    #pragma unroll 8
    for (int c = 0; c < C; c++) {
        float v = base[(size_t)c * HW];
        s += v * v;
    }
    float n = sqrtf(s);
    inv[lb * HW + p] = 1.0f / fmaxf(n, 1e-12f);
}

// ---------------- 2) scale + pack (fp32) in [b][k][p] layout ------------------
__global__ void pack_kernel(const float* __restrict__ x, const float* __restrict__ wts,
                            int which) {
    const float* inv = which ? g_invs : g_invq;
    float* out = which ? g_As : g_Aq;
    size_t idx = (size_t)blockIdx.x * blockDim.x + threadIdx.x;
    const size_t total = (size_t)L * B * C * HW;
    if (idx >= total) return;
    int l = (int)(idx / ((size_t)B * C * HW));
    size_t r = idx % ((size_t)B * C * HW);
    int b = (int)(r / ((size_t)C * HW));
    size_t r2 = r % ((size_t)C * HW);
    int c = (int)(r2 / HW);
    int p = (int)(r2 % HW);
    float w = which ? 1.0f : wts[l];
    float v = x[idx] * inv[(l * B + b) * HW + p] * w;
    out[((size_t)b * KD + (size_t)(l * C + c)) * HW + p] = v;
}

// ---------------- 3) big GEMM: red[b][q][s] = sum_k Aq[b][k][q]*As[b][k][s] ---
#define BM 128
#define BN 128
#define BK 16

__global__ __launch_bounds__(256) void gemm1_kernel() {
    int b = blockIdx.z;
    const float* A  = g_Aq + (size_t)b * KD * HW;
    const float* Bm = g_As + (size_t)b * KD * HW;
    float* Cc = g_red + (size_t)b * HW * HW;

    __shared__ float As[BK][BM];
    __shared__ float Bs[BK][BN];

    int m0 = blockIdx.x * BM;
    int n0 = blockIdx.y * BN;
    int tid = threadIdx.x;
    int tx = tid & 15;      // n direction
    int ty = tid >> 4;      // m direction

    float acc[8][8];
    #pragma unroll
    for (int i = 0; i < 8; i++)
        #pragma unroll
        for (int j = 0; j < 8; j++) acc[i][j] = 0.f;

    for (int k0 = 0; k0 < KD; k0 += BK) {
        #pragma unroll
        for (int jj = 0; jj < 8; jj++) {
            int i = tid + jj * 256;
            int kk = i >> 7;
            int mm = i & 127;
            int m = m0 + mm;
            int n = n0 + mm;
            As[kk][mm] = (m < HW) ? A[(size_t)(k0 + kk) * HW + m] : 0.f;
            Bs[kk][mm] = (n < HW) ? Bm[(size_t)(k0 + kk) * HW + n] : 0.f;
        }
        __syncthreads();
        #pragma unroll
        for (int kk = 0; kk < BK; kk++) {
            float a[8], bb[8];
            #pragma unroll
            for (int i = 0; i < 8; i++) a[i] = As[kk][ty * 8 + i];
            #pragma unroll
            for (int j = 0; j < 8; j++) bb[j] = Bs[kk][tx * 8 + j];
            #pragma unroll
            for (int i = 0; i < 8; i++)
                #pragma unroll
                for (int j = 0; j < 8; j++)
                    acc[i][j] += a[i] * bb[j];
        }
        __syncthreads();
    }

    #pragma unroll
    for (int i = 0; i < 8; i++) {
        int m = m0 + ty * 8 + i;
        if (m >= HW) continue;
        #pragma unroll
        for (int j = 0; j < 8; j++) {
            int n = n0 + tx * 8 + j;
            if (n < HW) Cc[(size_t)m * HW + n] = acc[i][j];
        }
    }
}

// ---------------- 4) row softmax over s (in-place, temp applied) --------------
__global__ __launch_bounds__(256) void softmax_kernel() {
    __shared__ float row[HW];
    __shared__ float sred[256];
    size_t base = (size_t)blockIdx.x * HW;   // blockIdx.x = b*HW + q
    int tid = threadIdx.x;

    float mx = -1e30f;
    for (int s = tid; s < HW; s += 256) {
        float v = g_red[base + s] * TEMP;
        row[s] = v;
        mx = fmaxf(mx, v);
    }
    sred[tid] = mx;
    __syncthreads();
    for (int st = 128; st > 0; st >>= 1) {
        if (tid < st) sred[tid] = fmaxf(sred[tid], sred[tid + st]);
        __syncthreads();
    }
    mx = sred[0];
    __syncthreads();

    float sm = 0.f;
    for (int s = tid; s < HW; s += 256) {
        float e = __expf(row[s] - mx);
        row[s] = e;
        sm += e;
    }
    sred[tid] = sm;
    __syncthreads();
    for (int st = 128; st > 0; st >>= 1) {
        if (tid < st) sred[tid] += sred[tid + st];
        __syncthreads();
    }
    float invs = 1.0f / sred[0];
    for (int s = tid; s < HW; s += 256)
        g_red[base + s] = row[s] * invs;
}

// ---------------- 5) attn GEMM + fused epilogue -------------------------------
// att_fq[b][c][q] = sum_s attn[b][q][s] * f_s[b][c][s]
#define BM2 64
#define BN2 64
#define BK2 32

__global__ __launch_bounds__(256) void gemm2_kernel(const float* __restrict__ v,
                                                    const float* __restrict__ fqin,
                                                    float* __restrict__ outfq,
                                                    float* __restrict__ outatt) {
    int b = blockIdx.z;
    const float* A  = g_red + (size_t)b * HW * HW;   // [q][s]
    const float* Bv = v + (size_t)b * CH * HW;       // [c][s]

    int m0 = blockIdx.x * BM2;   // q
    int n0 = blockIdx.y * BN2;   // c

    __shared__ float As[BM2][BK2 + 1];
    __shared__ float Bs[BN2][BK2 + 1];

    int tid = threadIdx.x;
    int tx = tid & 15;      // m (q) direction -> coalesced output
    int ty = tid >> 4;      // n (c) direction

    float acc[4][4];   // acc[j (n)][i (m)]
    #pragma unroll
    for (int j = 0; j < 4; j++)
        #pragma unroll
        for (int i = 0; i < 4; i++) acc[j][i] = 0.f;

    for (int k0 = 0; k0 < HW; k0 += BK2) {
        #pragma unroll
        for (int jj = 0; jj < 8; jj++) {
            int i = tid + jj * 256;
            int mm = i >> 5;
            int kk = i & 31;
            int m = m0 + mm;
            int k = k0 + kk;
            As[mm][kk] = (m < HW && k < HW) ? A[(size_t)m * HW + k] : 0.f;
            int n = n0 + mm;
            Bs[mm][kk] = (k < HW) ? Bv[(size_t)n * HW + k] : 0.f;
        }
        __syncthreads();
        #pragma unroll
        for (int kk = 0; kk < BK2; kk++) {
            float a[4], bb[4];
            #pragma unroll
            for (int i = 0; i < 4; i++) a[i] = As[tx * 4 + i][kk];
            #pragma unroll
            for (int j = 0; j < 4; j++) bb[j] = Bs[ty * 4 + j][kk];
            #pragma unroll
            for (int j = 0; j < 4; j++)
                #pragma unroll
                for (int i = 0; i < 4; i++)
                    acc[j][i] += a[i] * bb[j];
        }
        __syncthreads();
    }

    const float inv13 = 1.0f / (1.0f + ATT_WT);
    #pragma unroll
    for (int j = 0; j < 4; j++) {
        int n = n0 + ty * 4 + j;     // c (always < CH)
        #pragma unroll
        for (int i = 0; i < 4; i++) {
            int m = m0 + tx * 4 + i; // q
            if (m < HW) {
                size_t o = ((size_t)b * CH + n) * HW + m;
                float av = acc[j][i];
                outatt[o] = av;
                outfq[o] = (fqin[o] + av * ATT_WT) * inv13;
            }
        }
    }
}

// ---------------- launch ------------------------------------------------------
extern "C" void kernel_launch(void* const* d_in, const int* in_sizes, int n_in,
                              void* d_out, int out_size) {
    const float* fq_feats = (const float*)d_in[0];
    const float* fs_feats = (const float*)d_in[1];
    const float* f_q      = (const float*)d_in[2];
    const float* f_s      = (const float*)d_in[3];
    const float* w        = (const float*)d_in[4];

    float* outfq  = (float*)d_out;
    float* outatt = outfq + (size_t)B * CH * HW;

    // 1) inverse norms
    dim3 gN((HW + 255) / 256, L * B);
    norm_kernel<<<gN, 256>>>(fq_feats, 0);
    norm_kernel<<<gN, 256>>>(fs_feats, 1);

    // 2) pack (fp32) to [b][k][p]
    size_t total = (size_t)L * B * C * HW;
    int pb = (int)((total + 255) / 256);
    pack_kernel<<<pb, 256>>>(fq_feats, w, 0);
    pack_kernel<<<pb, 256>>>(fs_feats, w, 1);

    // 3) red = (w-scaled fq_n)^T @ fs_n   (M=N=3600, K=6144, per batch)
    dim3 g1((HW + BM - 1) / BM, (HW + BN - 1) / BN, B);
    gemm1_kernel<<<g1, 256>>>();

    // 4) softmax over support positions
    softmax_kernel<<<B * HW, 256>>>();

    // 5) attn @ v + epilogue
    dim3 g2((HW + BM2 - 1) / BM2, CH / BN2, B);
    gemm2_kernel<<<g2, 256>>>(f_s, f_q, outfq, outatt);
}

// round 12
// speedup vs baseline: 3.8646x; 3.8558x over previous
#include <cuda_runtime.h>
#include <cuda_fp16.h>
#include <cstdint>

// Problem constants
#define L 3
#define B 2
#define C 2048
#define HW 3600          // 60*60
#define CH 256
#define KD (L*C)         // 6144 fused K dimension
#define HWP 3712         // 29 * 128, padded spatial
#define TEMP 20.0f
#define ATT_WT 0.3f

#define BKK 32                  // fp16 k per pipeline stage
#define NCHUNK (KD / BKK)       // 192
#define ROWB 80                 // smem row stride in bytes (32 fp16 -> 64B + 16B pad)
#define TILEB (128 * ROWB)      // 10240 bytes per operand tile

// ---------------- scratch (static __device__ — no allocations) ----------------
__device__ __half g_Aq[(size_t)B * HWP * KD];   // [b][p][k]  w_l * normalized fq (fp16)
__device__ __half g_As[(size_t)B * HWP * KD];   // [b][p][k]  normalized fs (fp16)
__device__ float  g_red[(size_t)B * HWP * HWP]; // [b][q][s]  logits -> attn
__device__ float  g_invq[L * B * HW];
__device__ float  g_invs[L * B * HW];

// ======================= PTX helpers ==========================================
__device__ __forceinline__ uint32_t smem_u32(const void* p) {
    uint32_t a;
    asm("{ .reg .u64 t; cvta.to.shared.u64 t, %1; cvt.u32.u64 %0, t; }" : "=r"(a) : "l"(p));
    return a;
}
__device__ __forceinline__ void cpasync16(uint32_t dst, const void* src) {
    asm volatile("cp.async.cg.shared.global [%0], [%1], 16;"
        :: "r"(dst), "l"(__cvta_generic_to_global(src)) : "memory");
}
#define CP_COMMIT()  asm volatile("cp.async.commit_group;" ::: "memory")
#define CP_WAIT1()   asm volatile("cp.async.wait_group 1;" ::: "memory")
#define CP_WAIT0()   asm volatile("cp.async.wait_group 0;" ::: "memory")

__device__ __forceinline__ void ldsm_x4(uint32_t* r, uint32_t addr) {
    asm volatile("ldmatrix.sync.aligned.m8n8.x4.shared.b16 {%0,%1,%2,%3}, [%4];"
        : "=r"(r[0]), "=r"(r[1]), "=r"(r[2]), "=r"(r[3]) : "r"(addr));
}
__device__ __forceinline__ void ldsm_x2(uint32_t* r, uint32_t addr) {
    asm volatile("ldmatrix.sync.aligned.m8n8.x2.shared.b16 {%0,%1}, [%2];"
        : "=r"(r[0]), "=r"(r[1]) : "r"(addr));
}
__device__ __forceinline__ void mma16816(float* c, const uint32_t* a, const uint32_t* b) {
    asm volatile("mma.sync.aligned.m16n8k16.row.col.f32.f16.f16.f32 "
        "{%0,%1,%2,%3}, {%4,%5,%6,%7}, {%8,%9}, {%0,%1,%2,%3};"
        : "+f"(c[0]), "+f"(c[1]), "+f"(c[2]), "+f"(c[3])
        : "r"(a[0]), "r"(a[1]), "r"(a[2]), "r"(a[3]), "r"(b[0]), "r"(b[1]));
}

// ---------------- 1) inverse norms over C (coalesced over spatial) ------------
__global__ void norm_kernel(const float* __restrict__ x, int which) {
    float* inv = which ? g_invs : g_invq;
    int p = blockIdx.x * blockDim.x + threadIdx.x;
    int lb = blockIdx.y;                    // l*B + b
    if (p >= HW) return;
    const float* base = x + (size_t)lb * C * HW + p;
    float s = 0.f;
    #pragma unroll 8
    for (int c = 0; c < C; c++) {
        float v = base[(size_t)c * HW];
        s += v * v;
    }
    float n = sqrtf(s);
    inv[lb * HW + p] = 1.0f / fmaxf(n, 1e-12f);
}

// ---------------- 2) normalize + fp16 + transpose to [b][p][k] ----------------
// grid: (HWP/32, C/32, L*B), block (32, 8)
__global__ void pack_kernel(const float* __restrict__ x, const float* __restrict__ wts,
                            int which) {
    const float* inv = which ? g_invs : g_invq;
    __half* out = which ? g_As : g_Aq;
    int l = blockIdx.z / B;
    int b = blockIdx.z % B;
    int p0 = blockIdx.x * 32;
    int c0 = blockIdx.y * 32;
    int tx = threadIdx.x, ty = threadIdx.y;
    float w = which ? 1.0f : wts[l];

    __shared__ float tile[32][33];

    int p = p0 + tx;
    float iv = (p < HW) ? inv[(l * B + b) * HW + p] * w : 0.f;
    #pragma unroll
    for (int r = 0; r < 4; r++) {
        int c = c0 + ty + r * 8;
        float v = (p < HW) ? x[((size_t)(l * B + b) * C + c) * HW + p] * iv : 0.f;
        tile[ty + r * 8][tx] = v;
    }
    __syncthreads();

    #pragma unroll
    for (int r = 0; r < 4; r++) {
        int pp = p0 + ty + r * 8;
        int cc = c0 + tx;
        float v = tile[tx][ty + r * 8];
        out[((size_t)b * HWP + pp) * KD + (l * C + cc)] = __float2half(v);
    }
}

// ---------------- 3) HMMA GEMM: red[q][s] = sum_k Aq[q][k]*As[s][k] -----------
// CTA 128x128, 8 warps (2 M x 4 N), warp tile 64x32, BK=32, double buffered.
__global__ void __launch_bounds__(256) gemm1_mma_kernel() {
    __shared__ __align__(16) char sm[2 * 2 * TILEB];   // [buf][A|B] 40KB

    int tid  = threadIdx.x;
    int wid  = tid >> 5;
    int lane = tid & 31;
    int wm = wid & 1;        // 0..1 -> M
    int wn = wid >> 1;       // 0..3 -> N

    int m0 = blockIdx.x * 128;
    int n0 = blockIdx.y * 128;
    int b  = blockIdx.z;

    const __half* Ag = g_Aq + (size_t)b * HWP * KD + (size_t)m0 * KD;
    const __half* Bg = g_As + (size_t)b * HWP * KD + (size_t)n0 * KD;

    uint32_t sbase = smem_u32(sm);

    // cp.async loader: 128 rows x 64B per operand = 512 16B-chunks, 2 per thread
    int ld_row = tid >> 1;             // 0..127
    int ld_c2  = (tid & 1) * 2;        // chunks {0,1} or {2,3}

    auto load_chunk = [&](int chunk, int buf) {
        const __half* As_ = Ag + chunk * BKK;
        const __half* Bs_ = Bg + chunk * BKK;
        uint32_t a_s = sbase + buf * (2 * TILEB);
        uint32_t b_s = a_s + TILEB;
        uint32_t ro = ld_row * ROWB + ld_c2 * 16;
        cpasync16(a_s + ro,      As_ + (size_t)ld_row * KD + ld_c2 * 8);
        cpasync16(a_s + ro + 16, As_ + (size_t)ld_row * KD + ld_c2 * 8 + 8);
        cpasync16(b_s + ro,      Bs_ + (size_t)ld_row * KD + ld_c2 * 8);
        cpasync16(b_s + ro + 16, Bs_ + (size_t)ld_row * KD + ld_c2 * 8 + 8);
        CP_COMMIT();
    };

    float acc[4][4][4];
    #pragma unroll
    for (int i = 0; i < 4; i++)
        #pragma unroll
        for (int j = 0; j < 4; j++)
            #pragma unroll
            for (int k = 0; k < 4; k++) acc[i][j][k] = 0.f;

    // ldmatrix lane addressing
    int a_row   = lane & 15;
    int a_chunk = (lane >> 4) & 1;
    int b_row   = lane & 7;
    int b_chunk = (lane >> 3) & 1;

    load_chunk(0, 0);

    for (int i = 0; i < NCHUNK; i++) {
        int buf = i & 1;
        if (i + 1 < NCHUNK) {
            load_chunk(i + 1, buf ^ 1);
            CP_WAIT1();
        } else {
            CP_WAIT0();
        }
        __syncthreads();

        uint32_t a_s = sbase + buf * (2 * TILEB);
        uint32_t b_s = a_s + TILEB;

        #pragma unroll
        for (int ks = 0; ks < 2; ks++) {
            uint32_t afrag[4][4];
            uint32_t bfrag[4][2];
            #pragma unroll
            for (int mi = 0; mi < 4; mi++) {
                uint32_t addr = a_s + (uint32_t)(wm * 64 + mi * 16 + a_row) * ROWB
                              + ks * 32 + a_chunk * 16;
                ldsm_x4(afrag[mi], addr);
            }
            #pragma unroll
            for (int ni = 0; ni < 4; ni++) {
                uint32_t addr = b_s + (uint32_t)(wn * 32 + ni * 8 + b_row) * ROWB
                              + ks * 32 + b_chunk * 16;
                ldsm_x2(bfrag[ni], addr);
            }
            #pragma unroll
            for (int mi = 0; mi < 4; mi++)
                #pragma unroll
                for (int ni = 0; ni < 4; ni++)
                    mma16816(acc[mi][ni], afrag[mi], bfrag[ni]);
        }
        __syncthreads();
    }

    // epilogue: C fragment -> g_red (fp32). c0,c1 @ (t/4, 2(t%4)); c2,c3 @ (+8 row)
    int er = lane >> 2;
    int ec = (lane & 3) * 2;
    #pragma unroll
    for (int mi = 0; mi < 4; mi++) {
        int r_base = m0 + wm * 64 + mi * 16 + er;
        #pragma unroll
        for (int ni = 0; ni < 4; ni++) {
            int cidx = n0 + wn * 32 + ni * 8 + ec;
            float2* p0v = (float2*)&g_red[((size_t)b * HWP + r_base) * HWP + cidx];
            *p0v = make_float2(acc[mi][ni][0], acc[mi][ni][1]);
            float2* p1v = (float2*)&g_red[((size_t)b * HWP + r_base + 8) * HWP + cidx];
            *p1v = make_float2(acc[mi][ni][2], acc[mi][ni][3]);
        }
    }
}

// ---------------- 4) row softmax over s (in-place, temp applied) --------------
__global__ __launch_bounds__(256) void softmax_kernel() {
    __shared__ float row[HW];
    __shared__ float sred[256];
    int b = blockIdx.x / HW;
    int q = blockIdx.x % HW;
    size_t base = ((size_t)b * HWP + q) * HWP;
    int tid = threadIdx.x;

    float mx = -1e30f;
    for (int s = tid; s < HW; s += 256) {
        float v = g_red[base + s] * TEMP;
        row[s] = v;
        mx = fmaxf(mx, v);
    }
    sred[tid] = mx;
    __syncthreads();
    for (int st = 128; st > 0; st >>= 1) {
        if (tid < st) sred[tid] = fmaxf(sred[tid], sred[tid + st]);
        __syncthreads();
    }
    mx = sred[0];
    __syncthreads();

    float sm = 0.f;
    for (int s = tid; s < HW; s += 256) {
        float e = __expf(row[s] - mx);
        row[s] = e;
        sm += e;
    }
    sred[tid] = sm;
    __syncthreads();
    for (int st = 128; st > 0; st >>= 1) {
        if (tid < st) sred[tid] += sred[tid + st];
        __syncthreads();
    }
    float invs = 1.0f / sred[0];
    for (int s = tid; s < HW; s += 256)
        g_red[base + s] = row[s] * invs;
}

// ---------------- 5) attn GEMM + fused epilogue -------------------------------
// att_fq[b][c][q] = sum_s attn[b][q][s] * f_s[b][c][s]
#define BM2 64
#define BN2 64
#define BK2 32

__global__ __launch_bounds__(256) void gemm2_kernel(const float* __restrict__ v,
                                                    const float* __restrict__ fqin,
                                                    float* __restrict__ outfq,
                                                    float* __restrict__ outatt) {
    int b = blockIdx.z;
    const float* A  = g_red + (size_t)b * HWP * HWP;   // [q][s] stride HWP
    const float* Bv = v + (size_t)b * CH * HW;         // [c][s]

    int m0 = blockIdx.x * BM2;   // q
    int n0 = blockIdx.y * BN2;   // c

    __shared__ float As[BM2][BK2 + 1];
    __shared__ float Bs[BN2][BK2 + 1];

    int tid = threadIdx.x;
    int tx = tid & 15;      // m (q) -> coalesced output
    int ty = tid >> 4;      // n (c)

    float acc[4][4];
    #pragma unroll
    for (int j = 0; j < 4; j++)
        #pragma unroll
        for (int i = 0; i < 4; i++) acc[j][i] = 0.f;

    for (int k0 = 0; k0 < HW; k0 += BK2) {
        #pragma unroll
        for (int jj = 0; jj < 8; jj++) {
            int i = tid + jj * 256;
            int mm = i >> 5;
            int kk = i & 31;
            int m = m0 + mm;
            int k = k0 + kk;
            As[mm][kk] = (m < HW && k < HW) ? A[(size_t)m * HWP + k] : 0.f;
            int n = n0 + mm;
            Bs[mm][kk] = (k < HW) ? Bv[(size_t)n * HW + k] : 0.f;
        }
        __syncthreads();
        #pragma unroll
        for (int kk = 0; kk < BK2; kk++) {
            float a[4], bb[4];
            #pragma unroll
            for (int i = 0; i < 4; i++) a[i] = As[tx * 4 + i][kk];
            #pragma unroll
            for (int j = 0; j < 4; j++) bb[j] = Bs[ty * 4 + j][kk];
            #pragma unroll
            for (int j = 0; j < 4; j++)
                #pragma unroll
                for (int i = 0; i < 4; i++)
                    acc[j][i] += a[i] * bb[j];
        }
        __syncthreads();
    }

    const float inv13 = 1.0f / (1.0f + ATT_WT);
    #pragma unroll
    for (int j = 0; j < 4; j++) {
        int n = n0 + ty * 4 + j;
        #pragma unroll
        for (int i = 0; i < 4; i++) {
            int m = m0 + tx * 4 + i;
            if (m < HW) {
                size_t o = ((size_t)b * CH + n) * HW + m;
                float av = acc[j][i];
                outatt[o] = av;
                outfq[o] = (fqin[o] + av * ATT_WT) * inv13;
            }
        }
    }
}

// ---------------- launch ------------------------------------------------------
extern "C" void kernel_launch(void* const* d_in, const int* in_sizes, int n_in,
                              void* d_out, int out_size) {
    const float* fq_feats = (const float*)d_in[0];
    const float* fs_feats = (const float*)d_in[1];
    const float* f_q      = (const float*)d_in[2];
    const float* f_s      = (const float*)d_in[3];
    const float* w        = (const float*)d_in[4];

    float* outfq  = (float*)d_out;
    float* outatt = outfq + (size_t)B * CH * HW;

    // 1) inverse norms
    dim3 gN((HW + 255) / 256, L * B);
    norm_kernel<<<gN, 256>>>(fq_feats, 0);
    norm_kernel<<<gN, 256>>>(fs_feats, 1);

    // 2) normalize + fp16 + transpose to [b][p][k]
    dim3 gP(HWP / 32, C / 32, L * B);
    dim3 bP(32, 8);
    pack_kernel<<<gP, bP>>>(fq_feats, w, 0);
    pack_kernel<<<gP, bP>>>(fs_feats, w, 1);

    // 3) HMMA GEMM: red = Aq @ As^T  (M=N=3712, K=6144, per batch)
    dim3 g1(HWP / 128, HWP / 128, B);
    gemm1_mma_kernel<<<g1, 256>>>();

    // 4) softmax over support positions
    softmax_kernel<<<B * HW, 256>>>();

    // 5) attn @ v + epilogue
    dim3 g2((HW + BM2 - 1) / BM2, CH / BN2, B);
    gemm2_kernel<<<g2, 256>>>(f_s, f_q, outfq, outatt);
}

// round 13
// speedup vs baseline: 4.7403x; 1.2266x over previous
#include <cuda_runtime.h>
#include <cuda_fp16.h>
#include <cstdint>

// Problem constants
#define L 3
#define B 2
#define C 2048
#define HW 3600          // 60*60
#define CH 256
#define KD (L*C)         // 6144 fused K dimension
#define HWP 3712         // 29 * 128, padded spatial (gemm1 M/N, gemm2 N)
#define SP 3616          // 113 * 32, padded support dim for gemm2 K
#define TEMP 20.0f
#define ATT_WT 0.3f

#define BKK 32                  // fp16 k per pipeline stage
#define NCHUNK (KD / BKK)       // 192
#define NCHUNK2 (SP / BKK)      // 113
#define ROWB 80                 // smem row stride bytes (32 fp16 = 64B + 16B pad)
#define TILEB (128 * ROWB)      // 10240 bytes per operand tile
#define STAGES 4
#define SMEM_SZ (STAGES * 2 * TILEB)   // 81920

// ---------------- scratch (static __device__ — no allocations) ----------------
__device__ __half g_Aq[(size_t)B * HWP * KD];    // [b][p][k]  w_l * normalized fq
__device__ __half g_As[(size_t)B * HWP * KD];    // [b][p][k]  normalized fs
__device__ float  g_red[(size_t)B * HWP * HWP];  // [b][q][s]  logits (gemm1 out)
__device__ __half g_attnh[(size_t)B * HWP * SP]; // [b][q][s]  fp16 attn (padding rows stay 0)
__device__ __half g_vh[(size_t)B * CH * SP];     // [b][c][s]  fp16 f_s
__device__ float  g_invq[L * B * HW];
__device__ float  g_invs[L * B * HW];

// ======================= PTX helpers ==========================================
__device__ __forceinline__ uint32_t smem_u32(const void* p) {
    uint32_t a;
    asm("{ .reg .u64 t; cvta.to.shared.u64 t, %1; cvt.u32.u64 %0, t; }" : "=r"(a) : "l"(p));
    return a;
}
__device__ __forceinline__ void cpasync16(uint32_t dst, const void* src) {
    asm volatile("cp.async.cg.shared.global [%0], [%1], 16;"
        :: "r"(dst), "l"(__cvta_generic_to_global(src)) : "memory");
}
#define CP_COMMIT()  asm volatile("cp.async.commit_group;" ::: "memory")
#define CP_WAIT(n)   asm volatile("cp.async.wait_group %0;" :: "n"(n) : "memory")

__device__ __forceinline__ void ldsm_x4(uint32_t* r, uint32_t addr) {
    asm volatile("ldmatrix.sync.aligned.m8n8.x4.shared.b16 {%0,%1,%2,%3}, [%4];"
        : "=r"(r[0]), "=r"(r[1]), "=r"(r[2]), "=r"(r[3]) : "r"(addr));
}
__device__ __forceinline__ void ldsm_x2(uint32_t* r, uint32_t addr) {
    asm volatile("ldmatrix.sync.aligned.m8n8.x2.shared.b16 {%0,%1}, [%2];"
        : "=r"(r[0]), "=r"(r[1]) : "r"(addr));
}
__device__ __forceinline__ void mma16816(float* c, const uint32_t* a, const uint32_t* b) {
    asm volatile("mma.sync.aligned.m16n8k16.row.col.f32.f16.f16.f32 "
        "{%0,%1,%2,%3}, {%4,%5,%6,%7}, {%8,%9}, {%0,%1,%2,%3};"
        : "+f"(c[0]), "+f"(c[1]), "+f"(c[2]), "+f"(c[3])
        : "r"(a[0]), "r"(a[1]), "r"(a[2]), "r"(a[3]), "r"(b[0]), "r"(b[1]));
}

// ---------------- 1) inverse norms over C (coalesced over spatial) ------------
__global__ void norm_kernel(const float* __restrict__ x, int which) {
    float* inv = which ? g_invs : g_invq;
    int p = blockIdx.x * blockDim.x + threadIdx.x;
    int lb = blockIdx.y;                    // l*B + b
    if (p >= HW) return;
    const float* base = x + (size_t)lb * C * HW + p;
    float s = 0.f;
    #pragma unroll 8
    for (int c = 0; c < C; c++) {
        float v = base[(size_t)c * HW];
        s += v * v;
    }
    float n = sqrtf(s);
    inv[lb * HW + p] = 1.0f / fmaxf(n, 1e-12f);
}

// ---------------- 2) normalize + fp16 + transpose to [b][p][k] ----------------
// grid: (HWP/32, C/32, L*B), block (32, 8)
__global__ void pack_kernel(const float* __restrict__ x, const float* __restrict__ wts,
                            int which) {
    const float* inv = which ? g_invs : g_invq;
    __half* out = which ? g_As : g_Aq;
    int l = blockIdx.z / B;
    int b = blockIdx.z % B;
    int p0 = blockIdx.x * 32;
    int c0 = blockIdx.y * 32;
    int tx = threadIdx.x, ty = threadIdx.y;
    float w = which ? 1.0f : wts[l];

    __shared__ float tile[32][33];

    int p = p0 + tx;
    float iv = (p < HW) ? inv[(l * B + b) * HW + p] * w : 0.f;
    #pragma unroll
    for (int r = 0; r < 4; r++) {
        int c = c0 + ty + r * 8;
        float v = (p < HW) ? x[((size_t)(l * B + b) * C + c) * HW + p] * iv : 0.f;
        tile[ty + r * 8][tx] = v;
    }
    __syncthreads();

    #pragma unroll
    for (int r = 0; r < 4; r++) {
        int pp = p0 + ty + r * 8;
        int cc = c0 + tx;
        float v = tile[tx][ty + r * 8];
        out[((size_t)b * HWP + pp) * KD + (l * C + cc)] = __float2half(v);
    }
}

// ---------------- 2b) pack f_s to fp16 [b][c][s], zero-padded s ---------------
__global__ void pack_v_kernel(const float* __restrict__ v) {
    int idx = blockIdx.x * blockDim.x + threadIdx.x;
    if (idx >= B * CH * SP) return;
    int s = idx % SP;
    int bc = idx / SP;
    float val = (s < HW) ? v[(size_t)bc * HW + s] : 0.f;
    g_vh[idx] = __float2half(val);
}

// ============ shared HMMA mainloop (CTA 128x128, 8 warps 2Mx4N) ================
// A: rows m0..m0+127 of Ag (k-contiguous, stride lda halfs)
// Bt: rows n0..n0+127 of Bg (k-contiguous, stride ldb halfs)
// acc: [4][4][4] fp32, nchunk k-steps of 32.
__device__ __forceinline__ void mma_mainloop(const __half* Ag, const __half* Bg,
                                             size_t lda, size_t ldb, int nchunk,
                                             char* sm, float acc[4][4][4]) {
    int tid  = threadIdx.x;
    int wid  = tid >> 5;
    int lane = tid & 31;
    int wm = wid & 1;
    int wn = wid >> 1;

    uint32_t sbase = smem_u32(sm);
    int ld_row = tid >> 1;
    int ld_c2  = (tid & 1) * 2;

    auto load_chunk = [&](int chunk, int buf) {
        const __half* As_ = Ag + chunk * BKK;
        const __half* Bs_ = Bg + chunk * BKK;
        uint32_t a_s = sbase + buf * (2 * TILEB);
        uint32_t b_s = a_s + TILEB;
        uint32_t ro = ld_row * ROWB + ld_c2 * 16;
        cpasync16(a_s + ro,      As_ + (size_t)ld_row * lda + ld_c2 * 8);
        cpasync16(a_s + ro + 16, As_ + (size_t)ld_row * lda + ld_c2 * 8 + 8);
        cpasync16(b_s + ro,      Bs_ + (size_t)ld_row * ldb + ld_c2 * 8);
        cpasync16(b_s + ro + 16, Bs_ + (size_t)ld_row * ldb + ld_c2 * 8 + 8);
        CP_COMMIT();
    };

    int a_row   = lane & 15;
    int a_chunk = (lane >> 4) & 1;
    int b_row   = lane & 7;
    int b_chunk = (lane >> 3) & 1;

    // prologue: stages 0..STAGES-2
    #pragma unroll
    for (int s = 0; s < STAGES - 1; s++) load_chunk(s, s);

    for (int i = 0; i < nchunk; i++) {
        CP_WAIT(STAGES - 2);           // stage i resident
        __syncthreads();               // all warps done reading buf (i-1)%STAGES
        if (i + STAGES - 1 < nchunk) load_chunk(i + STAGES - 1, (i + STAGES - 1) % STAGES);
        else CP_COMMIT();              // keep group counting uniform

        int buf = i % STAGES;
        uint32_t a_s = sbase + buf * (2 * TILEB);
        uint32_t b_s = a_s + TILEB;

        #pragma unroll
        for (int ks = 0; ks < 2; ks++) {
            uint32_t afrag[4][4];
            uint32_t bfrag[4][2];
            #pragma unroll
            for (int mi = 0; mi < 4; mi++) {
                uint32_t addr = a_s + (uint32_t)(wm * 64 + mi * 16 + a_row) * ROWB
                              + ks * 32 + a_chunk * 16;
                ldsm_x4(afrag[mi], addr);
            }
            #pragma unroll
            for (int ni = 0; ni < 4; ni++) {
                uint32_t addr = b_s + (uint32_t)(wn * 32 + ni * 8 + b_row) * ROWB
                              + ks * 32 + b_chunk * 16;
                ldsm_x2(bfrag[ni], addr);
            }
            #pragma unroll
            for (int mi = 0; mi < 4; mi++)
                #pragma unroll
                for (int ni = 0; ni < 4; ni++)
                    mma16816(acc[mi][ni], afrag[mi], bfrag[ni]);
        }
    }
}

// ---------------- 3) gemm1: red[q][s] = sum_k Aq[q][k]*As[s][k] ---------------
__global__ void __launch_bounds__(256) gemm1_mma_kernel() {
    extern __shared__ __align__(16) char sm[];
    int m0 = blockIdx.x * 128;
    int n0 = blockIdx.y * 128;
    int b  = blockIdx.z;

    float acc[4][4][4];
    #pragma unroll
    for (int i = 0; i < 4; i++)
        #pragma unroll
        for (int j = 0; j < 4; j++)
            #pragma unroll
            for (int k = 0; k < 4; k++) acc[i][j][k] = 0.f;

    mma_mainloop(g_Aq + (size_t)b * HWP * KD + (size_t)m0 * KD,
                 g_As + (size_t)b * HWP * KD + (size_t)n0 * KD,
                 KD, KD, NCHUNK, sm, acc);

    int tid  = threadIdx.x;
    int wid  = tid >> 5;
    int lane = tid & 31;
    int wm = wid & 1, wn = wid >> 1;
    int er = lane >> 2;
    int ec = (lane & 3) * 2;
    #pragma unroll
    for (int mi = 0; mi < 4; mi++) {
        int r_base = m0 + wm * 64 + mi * 16 + er;
        #pragma unroll
        for (int ni = 0; ni < 4; ni++) {
            int cidx = n0 + wn * 32 + ni * 8 + ec;
            float2* p0v = (float2*)&g_red[((size_t)b * HWP + r_base) * HWP + cidx];
            *p0v = make_float2(acc[mi][ni][0], acc[mi][ni][1]);
            float2* p1v = (float2*)&g_red[((size_t)b * HWP + r_base + 8) * HWP + cidx];
            *p1v = make_float2(acc[mi][ni][2], acc[mi][ni][3]);
        }
    }
}

// ---------------- 4) row softmax over s -> fp16 attn (zero-padded) ------------
__global__ __launch_bounds__(256) void softmax_kernel() {
    __shared__ float row[HW];
    __shared__ float sred[256];
    int b = blockIdx.x / HW;
    int q = blockIdx.x % HW;
    size_t base = ((size_t)b * HWP + q) * HWP;
    int tid = threadIdx.x;

    float mx = -1e30f;
    for (int s = tid; s < HW; s += 256) {
        float v = g_red[base + s] * TEMP;
        row[s] = v;
        mx = fmaxf(mx, v);
    }
    sred[tid] = mx;
    __syncthreads();
    for (int st = 128; st > 0; st >>= 1) {
        if (tid < st) sred[tid] = fmaxf(sred[tid], sred[tid + st]);
        __syncthreads();
    }
    mx = sred[0];
    __syncthreads();

    float sm = 0.f;
    for (int s = tid; s < HW; s += 256) {
        float e = __expf(row[s] - mx);
        row[s] = e;
        sm += e;
    }
    sred[tid] = sm;
    __syncthreads();
    for (int st = 128; st > 0; st >>= 1) {
        if (tid < st) sred[tid] += sred[tid + st];
        __syncthreads();
    }
    float invs = 1.0f / sred[0];

    __half* out = g_attnh + ((size_t)b * HWP + q) * SP;
    for (int s = tid; s < SP; s += 256)
        out[s] = __float2half((s < HW) ? row[s] * invs : 0.f);
}

// ---------------- 5) gemm2 (HMMA): att_fq[c][q] = sum_s attn[q][s]*v[c][s] ----
// M = c (256), N = q (3712, masked to 3600), K = s (3616). Fused epilogue.
__global__ void __launch_bounds__(256) gemm2_mma_kernel(const float* __restrict__ fqin,
                                                        float* __restrict__ outfq,
                                                        float* __restrict__ outatt) {
    extern __shared__ __align__(16) char sm[];
    int m0 = blockIdx.x * 128;   // c
    int n0 = blockIdx.y * 128;   // q
    int b  = blockIdx.z;

    float acc[4][4][4];
    #pragma unroll
    for (int i = 0; i < 4; i++)
        #pragma unroll
        for (int j = 0; j < 4; j++)
            #pragma unroll
            for (int k = 0; k < 4; k++) acc[i][j][k] = 0.f;

    mma_mainloop(g_vh    + ((size_t)b * CH  + m0) * SP,
                 g_attnh + ((size_t)b * HWP + n0) * SP,
                 SP, SP, NCHUNK2, sm, acc);

    int tid  = threadIdx.x;
    int wid  = tid >> 5;
    int lane = tid & 31;
    int wm = wid & 1, wn = wid >> 1;
    int er = lane >> 2;
    int ec = (lane & 3) * 2;
    const float inv13 = 1.0f / (1.0f + ATT_WT);

    #pragma unroll
    for (int mi = 0; mi < 4; mi++) {
        int c0 = m0 + wm * 64 + mi * 16 + er;     // row c and c+8, both < 256
        #pragma unroll
        for (int ni = 0; ni < 4; ni++) {
            int q0 = n0 + wn * 32 + ni * 8 + ec;  // cols q0, q0+1
            if (q0 < HW) {
                size_t o0 = ((size_t)b * CH + c0) * HW + q0;
                float a0 = acc[mi][ni][0], a1 = acc[mi][ni][1];
                ((float2*)&outatt[o0])[0] = make_float2(a0, a1);
                float2 fq = *(const float2*)&fqin[o0];
                ((float2*)&outfq[o0])[0] =
                    make_float2((fq.x + a0 * ATT_WT) * inv13, (fq.y + a1 * ATT_WT) * inv13);

                size_t o1 = ((size_t)b * CH + c0 + 8) * HW + q0;
                float a2 = acc[mi][ni][2], a3 = acc[mi][ni][3];
                ((float2*)&outatt[o1])[0] = make_float2(a2, a3);
                float2 fq1 = *(const float2*)&fqin[o1];
                ((float2*)&outfq[o1])[0] =
                    make_float2((fq1.x + a2 * ATT_WT) * inv13, (fq1.y + a3 * ATT_WT) * inv13);
            }
        }
    }
}

// ---------------- launch ------------------------------------------------------
extern "C" void kernel_launch(void* const* d_in, const int* in_sizes, int n_in,
                              void* d_out, int out_size) {
    const float* fq_feats = (const float*)d_in[0];
    const float* fs_feats = (const float*)d_in[1];
    const float* f_q      = (const float*)d_in[2];
    const float* f_s      = (const float*)d_in[3];
    const float* w        = (const float*)d_in[4];

    float* outfq  = (float*)d_out;
    float* outatt = outfq + (size_t)B * CH * HW;

    static int smem_set = 0;
    if (!smem_set) {
        cudaFuncSetAttribute(gemm1_mma_kernel, cudaFuncAttributeMaxDynamicSharedMemorySize, SMEM_SZ);
        cudaFuncSetAttribute(gemm2_mma_kernel, cudaFuncAttributeMaxDynamicSharedMemorySize, SMEM_SZ);
        smem_set = 1;
    }

    // 1) inverse norms
    dim3 gN((HW + 255) / 256, L * B);
    norm_kernel<<<gN, 256>>>(fq_feats, 0);
    norm_kernel<<<gN, 256>>>(fs_feats, 1);

    // 2) normalize + fp16 + transpose; pack v
    dim3 gP(HWP / 32, C / 32, L * B);
    dim3 bP(32, 8);
    pack_kernel<<<gP, bP>>>(fq_feats, w, 0);
    pack_kernel<<<gP, bP>>>(fs_feats, w, 1);
    pack_v_kernel<<<(B * CH * SP + 255) / 256, 256>>>(f_s);

    // 3) HMMA gemm1: red = Aq @ As^T  (M=N=3712, K=6144, per batch)
    dim3 g1(HWP / 128, HWP / 128, B);
    gemm1_mma_kernel<<<g1, 256, SMEM_SZ>>>();

    // 4) softmax -> fp16 attn
    softmax_kernel<<<B * HW, 256>>>();

    // 5) HMMA gemm2 + fused epilogue
    dim3 g2(CH / 128, HWP / 128, B);
    gemm2_mma_kernel<<<g2, 256, SMEM_SZ>>>(f_q, outfq, outatt);
}